// round 7
// baseline (speedup 1.0000x reference)
#include <cuda_runtime.h>
#include <cuda_bf16.h>
#include <cstdint>

// Problem constants
#define BATCH 16384
#define NN    1024
#define NI    128
#define NO    64
#define REFRACTORY 0.9f

// Tiling
#define MT       32             // batch rows per CTA
#define KC       64             // k per chunk
#define NCHUNK   (NN / KC)      // 16
#define NTHREADS 256            // 8 warps: 2 m-groups(16 rows) x 4 n-groups(16 cols)
#define STAGES   4

// ---- dynamic smem layout ----
// [0,256)  bias[64] f32   [256,512) act[64] i32
// [1024+)  ring of STAGES A-stages, 8KB each (fp32, swizzled)
#define SMEM_BIAS    0
#define SMEM_ACT     256
#define SMEM_BUF0    1024
#define STAGE_STRIDE 8192
#define SMEM_TOTAL   (SMEM_BUF0 + STAGES * STAGE_STRIDE)   // 33792

// Pre-packed, tf32-rounded, refractory-folded weight slice.
// [chunk][warpn(4)][i(8)][lane(32)][4] — per warp per chunk: 8 coalesced
// LDG.128 at stride 512B.  Value (i,lane,j): v=i*4+j; ks=v>>2; nf=(v>>1)&1;
// p=v&1;  k = chunk*64+ks*8+(lane&3)+p*4;  n = warpn*16+nf*8+(lane>>2)
__device__ __align__(16) float g_Bpack[NCHUNK][4][8][32][4];

__device__ __forceinline__ uint32_t smem_u32(const void* p) {
    uint32_t a;
    asm("{ .reg .u64 t; cvta.to.shared.u64 t, %1; cvt.u32.u64 %0, t; }" : "=r"(a) : "l"(p));
    return a;
}
__device__ __forceinline__ void ldm_x4(uint32_t* r, uint32_t addr) {
    asm volatile("ldmatrix.sync.aligned.m8n8.x4.shared.b16 {%0,%1,%2,%3}, [%4];"
                 : "=r"(r[0]), "=r"(r[1]), "=r"(r[2]), "=r"(r[3]) : "r"(addr));
}
__device__ __forceinline__ void mma_tf32(float* d, const uint32_t* a, uint32_t b0, uint32_t b1) {
    asm volatile(
        "mma.sync.aligned.m16n8k8.row.col.f32.tf32.tf32.f32 "
        "{%0,%1,%2,%3}, {%4,%5,%6,%7}, {%8,%9}, {%0,%1,%2,%3};"
        : "+f"(d[0]), "+f"(d[1]), "+f"(d[2]), "+f"(d[3])
        : "r"(a[0]), "r"(a[1]), "r"(a[2]), "r"(a[3]), "r"(b0), "r"(b1));
}
__device__ __forceinline__ uint32_t cvt_tf32(uint32_t x) {
    uint32_t d;
    asm("cvt.rna.tf32.f32 %0, %1;" : "=r"(d) : "f"(__uint_as_float(x)));
    return d;
}
__device__ __forceinline__ void cp_async16(uint32_t smem_addr, const void* gptr) {
    asm volatile("cp.async.cg.shared.global [%0], [%1], 16;"
                 :: "r"(smem_addr), "l"(gptr) : "memory");
}
#define CP_COMMIT() asm volatile("cp.async.commit_group;" ::: "memory")
#define CP_WAIT2()  asm volatile("cp.async.wait_group 2;" ::: "memory")

// A stage: 32 rows x 16 units(16B); two 4KB halves (u<8 / u>=8).
// Conflict-free for cp.async stores and ldmatrix reads.
__device__ __forceinline__ uint32_t a_off(int row, int u) {
    return (uint32_t)((u >> 3) * 4096 + row * 128 + (((u & 7) ^ (row & 7)) << 4));
}

// ---------------- prep: round + fold + pack weight slice ----------------
// Thread idx = k*64+n -> coalesced 256B reads per W row; scattered writes.
__global__ void prep_kernel(const float* __restrict__ W) {
    int idx = blockIdx.x * blockDim.x + threadIdx.x;   // 0..65535
    if (idx >= NN * NO) return;
    int k = idx >> 6, n = idx & 63;
    int chunk = k >> 6, kl = k & 63;
    int ks = kl >> 3, p = (kl >> 2) & 1, l2 = kl & 3;
    int warpn = n >> 4, nl = n & 15, nf = nl >> 3, hi = nl & 7;
    int lane = hi * 4 + l2;
    int v = ks * 4 + nf * 2 + p;
    int i = v >> 2, j = v & 3;
    float f = (k >= NI && k < NN - NO) ? REFRACTORY : 1.0f;
    float val = W[(size_t)k * NN + (NN - NO) + n] * f;
    g_Bpack[chunk][warpn][i][lane][j] = __uint_as_float(cvt_tf32(__float_as_uint(val)));
}

// ---------------- activation ----------------
__device__ __forceinline__ float activate(float x, int a) {
    if (a == 0) return fmaxf(x, 0.0f);
    if (a == 1) { float r; asm("tanh.approx.f32 %0, %1;" : "=f"(r) : "f"(x)); return r; }
    if (a == 2) {
        float e, r;
        asm("ex2.approx.f32 %0, %1;" : "=f"(e) : "f"(-1.4426950408889634f * x));
        asm("rcp.approx.f32 %0, %1;" : "=f"(r) : "f"(1.0f + e));
        return r;
    }
    return x;
}

// ---------------- main kernel ----------------
__global__ void __launch_bounds__(NTHREADS, 4)
nn_tf32_kernel(const float* __restrict__ prev,    // [B, N]
               const float* __restrict__ inp,     // [B, I]
               const float* __restrict__ biases,  // [N]
               const int*   __restrict__ act,     // [N]
               float* __restrict__ out)           // [B, O]
{
    extern __shared__ unsigned char smem[];
    const uint32_t sb = smem_u32(smem);
    const int tid   = threadIdx.x;
    const int lane  = tid & 31;
    const int wid   = tid >> 5;
    const int warpm = wid >> 2;   // 0..1 (16 rows each)
    const int warpn = wid & 3;    // 0..3 (16 cols each)
    const int row0  = blockIdx.x * MT;

    float* sbias = (float*)(smem + SMEM_BIAS);
    int*   sact  = (int*)(smem + SMEM_ACT);
    if (tid < NO) {
        sbias[tid] = biases[NN - NO + tid];
        sact[tid]  = act[NN - NO + tid];
    }

    // issue A loads for one chunk into stage s
    auto issueA = [&](const float* src, int ldx, int s) {
        const uint32_t stage = sb + SMEM_BUF0 + s * STAGE_STRIDE;
#pragma unroll
        for (int i = 0; i < 2; ++i) {
            int g = tid + i * NTHREADS;          // 0..511
            int row = g >> 4, u = g & 15;
            cp_async16(stage + a_off(row, u), src + (size_t)row * ldx + u * 4);
        }
    };

    float acc[2][4];
#pragma unroll
    for (int nf = 0; nf < 2; ++nf)
#pragma unroll
        for (int i = 0; i < 4; ++i) acc[nf][i] = 0.0f;

    // prologue: chunks 0,1 (input), 2 (prev)
    issueA(inp  + (size_t)row0 * NI + 0 * KC, NI, 0); CP_COMMIT();
    issueA(inp  + (size_t)row0 * NI + 1 * KC, NI, 1); CP_COMMIT();
    issueA(prev + (size_t)row0 * NN + 2 * KC, NN, 2); CP_COMMIT();

    // B base for this warp: uint4 index = c*1024 + warpn*256 + i*32 + lane
    const uint4* bbase = (const uint4*)g_Bpack + warpn * 256 + lane;

    const int r0w = warpm * 16 + (lane & 15);
    const int uhi = lane >> 4;

    for (int c = 0; c < NCHUNK; ++c) {
        const int s = c & (STAGES - 1);
        const uint32_t stage = sb + SMEM_BUF0 + s * STAGE_STRIDE;
        const uint4* bp = bbase + c * 1024;

        // B head of ring (L2/L1-resident), issued before the wait
        uint4 bcur = __ldg(bp + 0 * 32);
        uint4 bnx  = __ldg(bp + 1 * 32);

        CP_WAIT2();            // chunk c's group complete
        __syncthreads();       // all warps past chunk c-1 -> stage (c+3)%4 free

        if (c + 3 < NCHUNK)
            issueA(prev + (size_t)row0 * NN + (c + 3) * KC, NN, (c + 3) & (STAGES - 1));
        CP_COMMIT();           // (possibly empty) keeps group accounting linear

#pragma unroll
        for (int ks = 0; ks < 8; ++ks) {
            uint4 bfut;
            if (ks + 2 < 8) bfut = __ldg(bp + (ks + 2) * 32);
            uint32_t a[4];
            ldm_x4(a, stage + a_off(r0w, 2 * ks + uhi));
#pragma unroll
            for (int q = 0; q < 4; ++q) a[q] = cvt_tf32(a[q]);
            mma_tf32(acc[0], a, bcur.x, bcur.y);   // nf=0: p=0,1
            mma_tf32(acc[1], a, bcur.z, bcur.w);   // nf=1: p=0,1
            bcur = bnx; bnx = bfut;
        }
    }

    // ---- epilogue: bias + heterogeneous activation + store ----
#pragma unroll
    for (int nf = 0; nf < 2; ++nf) {
        int col = warpn * 16 + nf * 8 + (lane & 3) * 2;
        int rg  = row0 + warpm * 16 + (lane >> 2);
        float b0 = sbias[col], b1 = sbias[col + 1];
        int   a0 = sact[col],  a1 = sact[col + 1];
        float2 o;
        o.x = activate(acc[nf][0] + b0, a0);
        o.y = activate(acc[nf][1] + b1, a1);
        *(float2*)(out + (size_t)rg * NO + col) = o;
        o.x = activate(acc[nf][2] + b0, a0);
        o.y = activate(acc[nf][3] + b1, a1);
        *(float2*)(out + (size_t)(rg + 8) * NO + col) = o;
    }
}

extern "C" void kernel_launch(void* const* d_in, const int* in_sizes, int n_in,
                              void* d_out, int out_size) {
    (void)in_sizes; (void)n_in; (void)out_size;
    const float* prev   = (const float*)d_in[0];  // [16384,1024]
    const float* inp    = (const float*)d_in[1];  // [16384,128]
    const float* W      = (const float*)d_in[2];  // [1024,1024]
    const float* biases = (const float*)d_in[3];  // [1024]
    const int*   act    = (const int*)d_in[4];    // [1024]
    float* out = (float*)d_out;                   // [16384,64]

    cudaFuncSetAttribute(nn_tf32_kernel, cudaFuncAttributeMaxDynamicSharedMemorySize, SMEM_TOTAL);

    prep_kernel<<<256, 256>>>(W);
    nn_tf32_kernel<<<BATCH / MT, NTHREADS, SMEM_TOTAL>>>(prev, inp, biases, act, out);
}

// round 8
// speedup vs baseline: 1.0755x; 1.0755x over previous
#include <cuda_runtime.h>
#include <cstdint>

// Problem constants
#define BATCH 16384
#define NN    1024
#define NI    128
#define NO    64
#define REFRACTORY 0.9f

#define KC       64
#define NCHUNK   (NN / KC)          // 16
#define NUNITS   (BATCH / 16)       // 1024 16-row units
#define NTHREADS 256                // 8 warps, each independent
#define GRID     152                // >= SM count; persistent-ish, queue-balanced

// per-warp private A ring: 4 stages x 4KB (16 rows x 64 fp32, swizzled)
#define STAGES      4
#define STAGE_BYTES 4096
#define WARP_SMEM   (STAGES * STAGE_BYTES)
#define SMEM_TOTAL  (8 * WARP_SMEM)     // 131072

// B packed for direct warp-wide LDG.128:
// uint4 index = ((chunk*8 + ks)*4 + ntp)*32 + lane ; 4 floats =
//   {nt=2ntp:b0, nt=2ntp:b1, nt=2ntp+1:b0, nt=2ntp+1:b1}
// b0: k = chunk*64+ks*8+(lane&3),  b1: k+4 ;  n = nt*8 + (lane>>2)
__device__ __align__(16) float g_Bpack[NCHUNK * 8 * 4 * 32 * 4];
__device__ unsigned g_unit_ctr;

__device__ __forceinline__ uint32_t smem_u32(const void* p) {
    uint32_t a;
    asm("{ .reg .u64 t; cvta.to.shared.u64 t, %1; cvt.u32.u64 %0, t; }" : "=r"(a) : "l"(p));
    return a;
}
__device__ __forceinline__ void ldm_x4(uint32_t* r, uint32_t addr) {
    asm volatile("ldmatrix.sync.aligned.m8n8.x4.shared.b16 {%0,%1,%2,%3}, [%4];"
                 : "=r"(r[0]), "=r"(r[1]), "=r"(r[2]), "=r"(r[3]) : "r"(addr));
}
__device__ __forceinline__ void mma_tf32(float* d, const uint32_t* a, uint32_t b0, uint32_t b1) {
    asm volatile(
        "mma.sync.aligned.m16n8k8.row.col.f32.tf32.tf32.f32 "
        "{%0,%1,%2,%3}, {%4,%5,%6,%7}, {%8,%9}, {%0,%1,%2,%3};"
        : "+f"(d[0]), "+f"(d[1]), "+f"(d[2]), "+f"(d[3])
        : "r"(a[0]), "r"(a[1]), "r"(a[2]), "r"(a[3]), "r"(b0), "r"(b1));
}
__device__ __forceinline__ uint32_t cvt_tf32(uint32_t x) {
    uint32_t d;
    asm("cvt.rna.tf32.f32 %0, %1;" : "=r"(d) : "f"(__uint_as_float(x)));
    return d;
}
__device__ __forceinline__ void cp_async16(uint32_t smem_addr, const void* gptr) {
    asm volatile("cp.async.cg.shared.global [%0], [%1], 16;"
                 :: "r"(smem_addr), "l"(gptr) : "memory");
}
#define CP_COMMIT() asm volatile("cp.async.commit_group;" ::: "memory")
#define CP_WAIT2()  asm volatile("cp.async.wait_group 2;" ::: "memory")

// A stage: 16 rows x 16 units(16B); swizzled, conflict-free for cp.async
// stores and ldmatrix reads.
__device__ __forceinline__ uint32_t a_off(int row, int u) {
    return (uint32_t)(((u >> 3) << 11) + (row << 7) + (((u & 7) ^ (row & 7)) << 4));
}

// ---------------- prep: reset queue + round/fold/pack weight slice ----------------
__global__ void prep_kernel(const float* __restrict__ W) {
    int idx = blockIdx.x * blockDim.x + threadIdx.x;   // 0..65535
    if (idx == 0) g_unit_ctr = 0;
    if (idx >= NN * NO) return;
    int j     = idx & 3;
    int lane  = (idx >> 2) & 31;
    int ntp   = (idx >> 7) & 3;
    int ks    = (idx >> 9) & 7;
    int chunk = idx >> 12;
    int nt = 2 * ntp + (j >> 1);
    int k  = chunk * 64 + ks * 8 + (lane & 3) + (j & 1) * 4;
    int n  = nt * 8 + (lane >> 2);
    float f = (k >= NI && k < NN - NO) ? REFRACTORY : 1.0f;
    float val = W[(size_t)k * NN + (NN - NO) + n] * f;
    g_Bpack[idx] = __uint_as_float(cvt_tf32(__float_as_uint(val)));
}

// ---------------- activation ----------------
__device__ __forceinline__ float activate(float x, int a) {
    if (a == 0) return fmaxf(x, 0.0f);
    if (a == 1) { float r; asm("tanh.approx.f32 %0, %1;" : "=f"(r) : "f"(x)); return r; }
    if (a == 2) {
        float e, r;
        asm("ex2.approx.f32 %0, %1;" : "=f"(e) : "f"(-1.4426950408889634f * x));
        asm("rcp.approx.f32 %0, %1;" : "=f"(r) : "f"(1.0f + e));
        return r;
    }
    return x;
}

// ---------------- main kernel: warp-private pipelines, no block sync ----------------
__global__ void __launch_bounds__(NTHREADS, 1)
nn_tf32_kernel(const float* __restrict__ prev,    // [B, N]
               const float* __restrict__ inp,     // [B, I]
               const float* __restrict__ biases,  // [N]
               const int*   __restrict__ act,     // [N]
               float* __restrict__ out)           // [B, O]
{
    extern __shared__ unsigned char smem[];
    const int lane = threadIdx.x & 31;
    const int wid  = threadIdx.x >> 5;
    const uint32_t wbase = smem_u32(smem) + wid * WARP_SMEM;

    const int arow = lane & 15;      // ldmatrix row
    const int auhi = lane >> 4;      // ldmatrix unit-half

    for (;;) {
        // ---- grab one 16-row unit from the queue ----
        unsigned unit;
        if (lane == 0) unit = atomicAdd(&g_unit_ctr, 1u);
        unit = __shfl_sync(0xffffffffu, unit, 0);
        if (unit >= NUNITS) break;
        const int row0 = (int)unit * 16;

        float acc[8][4];
#pragma unroll
        for (int nt = 0; nt < 8; ++nt)
#pragma unroll
            for (int i = 0; i < 4; ++i) acc[nt][i] = 0.0f;

        // issue A chunk c into stage s (8 cp.async16 per thread, warp-private)
        auto issueA = [&](int c, int s) {
            const float* src;
            int ldx;
            if (c < 2) { src = inp  + (size_t)row0 * NI + c * KC; ldx = NI; }
            else       { src = prev + (size_t)row0 * NN + c * KC; ldx = NN; }
            const uint32_t stage = wbase + s * STAGE_BYTES;
#pragma unroll
            for (int i = 0; i < 8; ++i) {
                int g = lane + i * 32;          // 0..255
                int row = g >> 4, u = g & 15;
                cp_async16(stage + a_off(row, u), src + (size_t)row * ldx + u * 4);
            }
        };

        // prologue: chunks 0,1,2 -> stages 0,1,2 (3 groups)
        issueA(0, 0); CP_COMMIT();
        issueA(1, 1); CP_COMMIT();
        issueA(2, 2); CP_COMMIT();

        for (int c = 0; c < NCHUNK; ++c) {
            const uint32_t stage = wbase + (c & (STAGES - 1)) * STAGE_BYTES;
            // B chunk base: uint4 idx = ((c*8+ks)*4+ntp)*32 + lane
            const uint4* bp = (const uint4*)g_Bpack + (size_t)c * 1024 + lane;

            // prefetch B ks=0 before the A wait (L1/L2-resident)
            uint4 bq[4];
#pragma unroll
            for (int t = 0; t < 4; ++t) bq[t] = __ldg(bp + t * 32);

            CP_WAIT2();                 // FIFO retire -> chunk c's group done
            if (c + 3 < NCHUNK) issueA(c + 3, (c + 3) & (STAGES - 1));
            CP_COMMIT();                // keep per-thread group accounting linear

#pragma unroll
            for (int ks = 0; ks < 8; ++ks) {
                uint4 bn[4];
                if (ks < 7) {
                    const uint4* bpn = bp + (ks + 1) * 128;
#pragma unroll
                    for (int t = 0; t < 4; ++t) bn[t] = __ldg(bpn + t * 32);
                }
                uint32_t a[4];
                ldm_x4(a, stage + a_off(arow, 2 * ks + auhi));
#pragma unroll
                for (int q = 0; q < 4; ++q) a[q] = cvt_tf32(a[q]);
#pragma unroll
                for (int ntp = 0; ntp < 4; ++ntp) {
                    mma_tf32(acc[2 * ntp + 0], a, bq[ntp].x, bq[ntp].y);
                    mma_tf32(acc[2 * ntp + 1], a, bq[ntp].z, bq[ntp].w);
                }
#pragma unroll
                for (int t = 0; t < 4; ++t) bq[t] = bn[t];
            }
        }

        // ---- epilogue: bias + heterogeneous activation + store ----
        const int rg = row0 + (lane >> 2);
#pragma unroll
        for (int nt = 0; nt < 8; ++nt) {
            int col = nt * 8 + (lane & 3) * 2;
            float b0 = __ldg(biases + NN - NO + col);
            float b1 = __ldg(biases + NN - NO + col + 1);
            int   a0 = __ldg(act + NN - NO + col);
            int   a1 = __ldg(act + NN - NO + col + 1);
            float2 o;
            o.x = activate(acc[nt][0] + b0, a0);
            o.y = activate(acc[nt][1] + b1, a1);
            *(float2*)(out + (size_t)rg * NO + col) = o;
            o.x = activate(acc[nt][2] + b0, a0);
            o.y = activate(acc[nt][3] + b1, a1);
            *(float2*)(out + (size_t)(rg + 8) * NO + col) = o;
        }
    }
}

extern "C" void kernel_launch(void* const* d_in, const int* in_sizes, int n_in,
                              void* d_out, int out_size) {
    (void)in_sizes; (void)n_in; (void)out_size;
    const float* prev   = (const float*)d_in[0];  // [16384,1024]
    const float* inp    = (const float*)d_in[1];  // [16384,128]
    const float* W      = (const float*)d_in[2];  // [1024,1024]
    const float* biases = (const float*)d_in[3];  // [1024]
    const int*   act    = (const int*)d_in[4];    // [1024]
    float* out = (float*)d_out;                   // [16384,64]

    cudaFuncSetAttribute(nn_tf32_kernel, cudaFuncAttributeMaxDynamicSharedMemorySize, SMEM_TOTAL);

    prep_kernel<<<256, 256>>>(W);
    nn_tf32_kernel<<<GRID, NTHREADS, SMEM_TOTAL>>>(prev, inp, biases, act, out);
}